// round 9
// baseline (speedup 1.0000x reference)
#include <cuda_runtime.h>
#include <cuda_bf16.h>
#include <math_constants.h>

// Problem constants
#define B_    32
#define C_    64
#define HW_   4096
#define CHW_  262144
#define NPTS  131072
#define K_    2048
#define TPB   128
#define NBLK  (NPTS/TPB)      // 1024
#define CHUNK 32              // codes per MMA chunk
#define NCH   (K_/CHUNK)      // 64
#define EPS   2.0e-3f         // screening margin; > 3*delta(bf16) ~ 1e-3

// Scratch (__device__ globals: allocation-free)
__device__ float    g_ee[K_];
__device__ float    g_zz[NPTS];
__device__ float    g_zf32[NPTS * C_];       // z transposed fp32 (32MB)
__device__ unsigned g_zbf[NPTS * C_ / 2];    // z bf16 pairs (16MB)
__device__ unsigned g_ebf[K_ * C_ / 2];      // codebook bf16 pairs
__device__ int      g_bidx[NPTS];
__device__ float    g_partials[NBLK];

// Packed fp32x2 FMA + pack/unpack
__device__ __forceinline__ void ffma2(unsigned long long& acc,
                                      unsigned long long a,
                                      unsigned long long b) {
    asm("fma.rn.f32x2 %0, %1, %2, %0;" : "+l"(acc) : "l"(a), "l"(b));
}
__device__ __forceinline__ void unpack2(unsigned long long v, float& lo, float& hi) {
    asm("mov.b64 {%0, %1}, %2;" : "=f"(lo), "=f"(hi) : "l"(v));
}
__device__ __forceinline__ unsigned long long pack2(float lo, float hi) {
    unsigned long long v;
    asm("mov.b64 %0, {%1, %2};" : "=l"(v) : "f"(lo), "f"(hi));
    return v;
}
__device__ __forceinline__ unsigned bfpack(float lo, float hi) {
    unsigned short a = __bfloat16_as_ushort(__float2bfloat16(lo));
    unsigned short b = __bfloat16_as_ushort(__float2bfloat16(hi));
    return (unsigned)a | ((unsigned)b << 16);
}
__device__ __forceinline__ unsigned long long umin64(unsigned long long a,
                                                     unsigned long long b) {
    return a < b ? a : b;
}

// bf16 m16n8k16 MMA, fp32 accumulate (layout validated: rel_err 0.0)
__device__ __forceinline__ void mma16816(float& c0, float& c1, float& c2, float& c3,
                                         unsigned a0, unsigned a1, unsigned a2, unsigned a3,
                                         unsigned b0, unsigned b1) {
    asm volatile(
        "mma.sync.aligned.m16n8k16.row.col.f32.bf16.bf16.f32 "
        "{%0,%1,%2,%3}, {%4,%5,%6,%7}, {%8,%9}, {%0,%1,%2,%3};"
        : "+f"(c0), "+f"(c1), "+f"(c2), "+f"(c3)
        : "r"(a0), "r"(a1), "r"(a2), "r"(a3), "r"(b0), "r"(b1));
}

// ---------------------------------------------------------------------------
// Exact recheck (bit-identical to validated pipeline), returns packed
// (ordered_float(d) << 32) | k so a 64-bit min is a lexicographic (d, k) min
// == first-occurrence-in-ascending-k argmin. __noinline__: rare call, keeps
// the hot loop small.
// ---------------------------------------------------------------------------
__device__ __noinline__ unsigned long long exact_pack(
    const float* __restrict__ ew, int row, int k, float eek, float zz)
{
    const float4* zr = (const float4*)(g_zf32 + (size_t)row * C_);
    const float4* er = (const float4*)(ew + (size_t)k * C_);
    unsigned long long a0 = 0ull, a1 = 0ull;
#pragma unroll
    for (int c4 = 0; c4 < 16; c4++) {
        float4 zv = zr[c4];
        float4 ev = __ldg(er + c4);
        ffma2(a0, pack2(zv.x, zv.y), pack2(ev.x, ev.y));
        ffma2(a1, pack2(zv.z, zv.w), pack2(ev.z, ev.w));
    }
    float x, y, u, w;
    unpack2(a0, x, y); unpack2(a1, u, w);
    float dot = (x + y) + (u + w);
    float d = fmaf(-2.0f, dot, zz + eek);
    unsigned ub = __float_as_uint(d);
    ub ^= (ub & 0x80000000u) ? 0xFFFFFFFFu : 0x80000000u;  // order-preserving
    return ((unsigned long long)ub << 32) | (unsigned)k;
}

// ---------------------------------------------------------------------------
// Prep: transpose z -> fp32 + bf16 scratch; exact zz (validated structure)
// ---------------------------------------------------------------------------
__global__ __launch_bounds__(TPB)
void prep_kernel(const float* __restrict__ z) {
    const int tid = threadIdx.x;
    const int p0  = blockIdx.x * TPB;
    const int b   = p0 / HW_;
    const int hw0 = p0 - b * HW_;
    const int p   = p0 + tid;
    const float* zp = z + (size_t)b * CHW_ + (hw0 + tid);

    float f[C_];
#pragma unroll
    for (int c = 0; c < C_; c++) f[c] = zp[(size_t)c * HW_];

    unsigned long long a0 = 0ull, a1 = 0ull;
#pragma unroll
    for (int c4 = 0; c4 < 16; c4++) {
        ffma2(a0, pack2(f[4*c4+0], f[4*c4+1]), pack2(f[4*c4+0], f[4*c4+1]));
        ffma2(a1, pack2(f[4*c4+2], f[4*c4+3]), pack2(f[4*c4+2], f[4*c4+3]));
    }
    float x, y, u, v;
    unpack2(a0, x, y); unpack2(a1, u, v);
    g_zz[p] = (x + y) + (u + v);

    float4* zf = (float4*)(g_zf32 + (size_t)p * C_);
#pragma unroll
    for (int i = 0; i < 16; i++)
        zf[i] = make_float4(f[4*i], f[4*i+1], f[4*i+2], f[4*i+3]);

    unsigned* zb = g_zbf + (size_t)p * (C_/2);
#pragma unroll
    for (int w = 0; w < 32; w++) zb[w] = bfpack(f[2*w], f[2*w+1]);
}

// ---------------------------------------------------------------------------
// Prep codebook: exact ee + bf16 conversion
// ---------------------------------------------------------------------------
__global__ void eprep_kernel(const float* __restrict__ ew) {
    int k = blockIdx.x * blockDim.x + threadIdx.x;
    if (k >= K_) return;
    const float4* r = reinterpret_cast<const float4*>(ew + (size_t)k * C_);
    float4 a = make_float4(0.f, 0.f, 0.f, 0.f);
    float f[C_];
#pragma unroll
    for (int c4 = 0; c4 < 16; c4++) {
        float4 e = r[c4];
        f[4*c4] = e.x; f[4*c4+1] = e.y; f[4*c4+2] = e.z; f[4*c4+3] = e.w;
        a.x = fmaf(e.x, e.x, a.x);
        a.y = fmaf(e.y, e.y, a.y);
        a.z = fmaf(e.z, e.z, a.z);
        a.w = fmaf(e.w, e.w, a.w);
    }
    g_ee[k] = (a.x + a.y) + (a.z + a.w);
    unsigned* eb = g_ebf + (size_t)k * (C_/2);
#pragma unroll
    for (int w = 0; w < 32; w++) eb[w] = bfpack(f[2*w], f[2*w+1]);
}

// ---------------------------------------------------------------------------
// Fused MMA screen + exact recheck. Pass 0: per-row min of s~ (registers
// only). Pass 1: identical MMA; values under amin+EPS get an exact fp32
// recheck folded into a packed lexicographic (d, k) min.
// ---------------------------------------------------------------------------
__global__ __launch_bounds__(TPB)
void vq_fused_kernel(const float* __restrict__ ew) {
    __shared__ unsigned esmw[CHUNK * 36];
    __shared__ float    see[CHUNK];

    const int tid  = threadIdx.x;
    const int lane = tid & 31;
    const int wid  = tid >> 5;
    const int g    = lane >> 2;
    const int tig  = lane & 3;
    const int p0   = blockIdx.x * TPB;

    // A fragments (persistent across both passes): 2 m-tiles x 4 k-steps
    unsigned afr[2][4][4];
#pragma unroll
    for (int mt = 0; mt < 2; mt++) {
#pragma unroll
        for (int ks = 0; ks < 4; ks++) {
            int row0 = p0 + wid * 32 + mt * 16 + g;
            int row1 = row0 + 8;
            const unsigned* z0 = g_zbf + (size_t)row0 * 32 + ks * 8 + tig;
            const unsigned* z1 = g_zbf + (size_t)row1 * 32 + ks * 8 + tig;
            afr[mt][ks][0] = z0[0];
            afr[mt][ks][1] = z1[0];
            afr[mt][ks][2] = z0[4];
            afr[mt][ks][3] = z1[4];
        }
    }

    // Per-row zz (rows: [mt][r] -> p0 + wid*32 + mt*16 + g + r*8)
    float zzr[2][2];
#pragma unroll
    for (int mt = 0; mt < 2; mt++)
#pragma unroll
        for (int r = 0; r < 2; r++)
            zzr[mt][r] = g_zz[p0 + wid * 32 + mt * 16 + g + r * 8];

    float mn[2][2] = {{CUDART_INF_F, CUDART_INF_F}, {CUDART_INF_F, CUDART_INF_F}};
    float th[2][2];
    unsigned long long best[2][2] =
        {{~0ull, ~0ull}, {~0ull, ~0ull}};

    for (int pass = 0; pass < 2; pass++) {
        for (int ch = 0; ch < NCH; ch++) {
            __syncthreads();
#pragma unroll
            for (int t = tid; t < CHUNK * 8; t += TPB) {
                int r = t >> 3, wg = t & 7;
                uint4 v = ((const uint4*)g_ebf)[(size_t)(ch * CHUNK + r) * 8 + wg];
                *((uint4*)(esmw + r * 36 + wg * 4)) = v;
            }
            if (tid < CHUNK) see[tid] = g_ee[ch * CHUNK + tid];
            __syncthreads();

            float acc[2][4][4];
#pragma unroll
            for (int mt = 0; mt < 2; mt++)
#pragma unroll
                for (int nt = 0; nt < 4; nt++)
#pragma unroll
                    for (int i = 0; i < 4; i++) acc[mt][nt][i] = 0.f;

#pragma unroll
            for (int nt = 0; nt < 4; nt++) {
#pragma unroll
                for (int ks = 0; ks < 4; ks++) {
                    unsigned b0 = esmw[(nt * 8 + g) * 36 + ks * 8 + tig];
                    unsigned b1 = esmw[(nt * 8 + g) * 36 + ks * 8 + 4 + tig];
                    mma16816(acc[0][nt][0], acc[0][nt][1], acc[0][nt][2], acc[0][nt][3],
                             afr[0][ks][0], afr[0][ks][1], afr[0][ks][2], afr[0][ks][3],
                             b0, b1);
                    mma16816(acc[1][nt][0], acc[1][nt][1], acc[1][nt][2], acc[1][nt][3],
                             afr[1][ks][0], afr[1][ks][1], afr[1][ks][2], afr[1][ks][3],
                             b0, b1);
                }
            }

            // Epilogue
#pragma unroll
            for (int mt = 0; mt < 2; mt++) {
                const int row0 = p0 + wid * 32 + mt * 16 + g;
#pragma unroll
                for (int nt = 0; nt < 4; nt++) {
                    const float eA = see[nt * 8 + 2 * tig];
                    const float eB = see[nt * 8 + 2 * tig + 1];
                    const float s0 = fmaf(-2.0f, acc[mt][nt][0], eA);
                    const float s1 = fmaf(-2.0f, acc[mt][nt][1], eB);
                    const float s2 = fmaf(-2.0f, acc[mt][nt][2], eA);
                    const float s3 = fmaf(-2.0f, acc[mt][nt][3], eB);
                    if (pass == 0) {
                        mn[mt][0] = fminf(mn[mt][0], fminf(s0, s1));
                        mn[mt][1] = fminf(mn[mt][1], fminf(s2, s3));
                    } else {
                        const int kb = ch * CHUNK + nt * 8 + 2 * tig;
                        if (s0 < th[mt][0])
                            best[mt][0] = umin64(best[mt][0],
                                exact_pack(ew, row0, kb, eA, zzr[mt][0]));
                        if (s1 < th[mt][0])
                            best[mt][0] = umin64(best[mt][0],
                                exact_pack(ew, row0, kb + 1, eB, zzr[mt][0]));
                        if (s2 < th[mt][1])
                            best[mt][1] = umin64(best[mt][1],
                                exact_pack(ew, row0 + 8, kb, eA, zzr[mt][1]));
                        if (s3 < th[mt][1])
                            best[mt][1] = umin64(best[mt][1],
                                exact_pack(ew, row0 + 8, kb + 1, eB, zzr[mt][1]));
                    }
                }
            }
        }

        if (pass == 0) {
            // Reduce mins over the 4 tig lanes sharing each row (all lanes
            // end with the same value), then set thresholds.
#pragma unroll
            for (int mt = 0; mt < 2; mt++)
#pragma unroll
                for (int r = 0; r < 2; r++) {
                    float v = mn[mt][r];
                    v = fminf(v, __shfl_xor_sync(0xffffffffu, v, 1));
                    v = fminf(v, __shfl_xor_sync(0xffffffffu, v, 2));
                    th[mt][r] = v + EPS;
                }
        }
    }

    // Final: lexicographic (d, k) min across tig lanes; write index.
#pragma unroll
    for (int mt = 0; mt < 2; mt++)
#pragma unroll
        for (int r = 0; r < 2; r++) {
            unsigned long long v = best[mt][r];
            v = umin64(v, __shfl_xor_sync(0xffffffffu, v, 1));
            v = umin64(v, __shfl_xor_sync(0xffffffffu, v, 2));
            if (tig == 0) {
                int row = p0 + wid * 32 + mt * 16 + g + r * 8;
                g_bidx[row] = (int)(v & 0xffffffffull);
            }
        }
}

// ---------------------------------------------------------------------------
// Outputs: e-row gather via float4 into padded smem, transposed coalesced
// writes; loss partials exact (validated lane structure).
// ---------------------------------------------------------------------------
__global__ __launch_bounds__(TPB)
void out_kernel(const float* __restrict__ z, const float* __restrict__ ew,
                float* __restrict__ out, int out_size) {
    __shared__ float sq[TPB][C_ + 1];   // padded: conflict-free column reads
    __shared__ float sred[TPB];

    const int tid = threadIdx.x;
    const int p0  = blockIdx.x * TPB;
    const int b   = p0 / HW_;
    const int hw0 = p0 - b * HW_;
    const int p   = p0 + tid;

    const int bidx = g_bidx[p];

    const float4* zr   = (const float4*)(g_zf32 + (size_t)p * C_);
    const float4* erow = (const float4*)(ew + (size_t)bidx * C_);
    float4 al = make_float4(0.f, 0.f, 0.f, 0.f);
#pragma unroll
    for (int c4 = 0; c4 < 16; c4++) {
        float4 e  = __ldg(erow + c4);
        sq[tid][4*c4 + 0] = e.x;
        sq[tid][4*c4 + 1] = e.y;
        sq[tid][4*c4 + 2] = e.z;
        sq[tid][4*c4 + 3] = e.w;
        float4 zv = zr[c4];
        float dx = e.x - zv.x; al.x = fmaf(dx, dx, al.x);
        float dy = e.y - zv.y; al.y = fmaf(dy, dy, al.y);
        float dz = e.z - zv.z; al.z = fmaf(dz, dz, al.z);
        float dw = e.w - zv.w; al.w = fmaf(dw, dw, al.w);
    }
    sred[tid] = (al.x + al.y) + (al.z + al.w);
    __syncthreads();                 // publishes sq + sred
#pragma unroll
    for (int s = TPB / 2; s > 0; s >>= 1) {
        if (tid < s) sred[tid] += sred[tid + s];
        __syncthreads();
    }
    if (tid == 0) g_partials[blockIdx.x] = sred[0];

    // straight-through z + (q - z), transposed to (B,C,H,W), coalesced
    const size_t obase = (size_t)b * CHW_ + hw0;
#pragma unroll 4
    for (int c = 0; c < C_; c++) {
        size_t gi = obase + (size_t)c * HW_ + tid;
        float zv = z[gi];
        out[gi] = zv + (sq[tid][c] - zv);
    }

    if ((long long)out_size >= (long long)NPTS * C_ + NPTS)
        out[(size_t)NPTS * C_ + p0 + tid] = (float)bidx;
}

// ---------------------------------------------------------------------------
// Deterministic final loss reduction
// ---------------------------------------------------------------------------
__global__ void loss_kernel(float* __restrict__ out, int out_size) {
    __shared__ double sd[256];
    int tid = threadIdx.x;
    double s = 0.0;
#pragma unroll
    for (int j = 0; j < NBLK / 256; j++)
        s += (double)g_partials[tid * (NBLK / 256) + j];
    sd[tid] = s;
    __syncthreads();
#pragma unroll
    for (int st = 128; st > 0; st >>= 1) {
        if (tid < st) sd[tid] += sd[tid + st];
        __syncthreads();
    }
    if (tid == 0 && (long long)out_size >= (long long)NPTS * C_ + NPTS + 1)
        out[(size_t)NPTS * C_ + NPTS] =
            (float)(0.25 * sd[0] / (double)((size_t)NPTS * C_));
}

// ---------------------------------------------------------------------------
extern "C" void kernel_launch(void* const* d_in, const int* in_sizes, int n_in,
                              void* d_out, int out_size)
{
    const float* z  = (const float*)d_in[0];   // (32, 64, 64, 64) f32
    const float* ew = (const float*)d_in[1];   // (2048, 64) f32
    float* out = (float*)d_out;

    prep_kernel<<<NBLK, TPB>>>(z);
    eprep_kernel<<<(K_ + 127) / 128, 128>>>(ew);
    vq_fused_kernel<<<NBLK, TPB>>>(ew);
    out_kernel<<<NBLK, TPB>>>(z, ew, out, out_size);
    loss_kernel<<<1, 256>>>(out, out_size);
}

// round 10
// speedup vs baseline: 1.5944x; 1.5944x over previous
#include <cuda_runtime.h>
#include <cuda_bf16.h>
#include <cuda_fp16.h>
#include <math_constants.h>

// Problem constants
#define B_    32
#define C_    64
#define HW_   4096
#define CHW_  262144
#define NPTS  131072
#define K_    2048
#define TPB   128
#define NBLK  (NPTS/TPB)      // 1024
#define CHUNK 32              // codes per MMA chunk
#define NCH   (K_/CHUNK)      // 64
#define EPS   2.0e-3f         // screening margin; >> 2*delta(bf16)+fp16 quant

// Scratch (__device__ globals: allocation-free)
__device__ float    g_ee[K_];
__device__ float    g_zz[NPTS];
__device__ float    g_zf32[NPTS * C_];       // z transposed fp32 (32MB)
__device__ unsigned g_zbf[NPTS * C_ / 2];    // z bf16 pairs (16MB)
__device__ unsigned g_ebf[K_ * C_ / 2];      // codebook bf16 pairs
__device__ __half   g_s[(size_t)NPTS * K_];  // s~ = ee-2*dot~, fp16 (512MB)
__device__ float    g_amin[NPTS];            // per-point min of s~
__device__ int      g_bidx[NPTS];
__device__ float    g_partials[NBLK];

// Packed fp32x2 FMA + pack/unpack
__device__ __forceinline__ void ffma2(unsigned long long& acc,
                                      unsigned long long a,
                                      unsigned long long b) {
    asm("fma.rn.f32x2 %0, %1, %2, %0;" : "+l"(acc) : "l"(a), "l"(b));
}
__device__ __forceinline__ void unpack2(unsigned long long v, float& lo, float& hi) {
    asm("mov.b64 {%0, %1}, %2;" : "=f"(lo), "=f"(hi) : "l"(v));
}
__device__ __forceinline__ unsigned long long pack2(float lo, float hi) {
    unsigned long long v;
    asm("mov.b64 %0, {%1, %2};" : "=l"(v) : "f"(lo), "f"(hi));
    return v;
}
__device__ __forceinline__ unsigned bfpack(float lo, float hi) {
    unsigned short a = __bfloat16_as_ushort(__float2bfloat16(lo));
    unsigned short b = __bfloat16_as_ushort(__float2bfloat16(hi));
    return (unsigned)a | ((unsigned)b << 16);
}
__device__ __forceinline__ unsigned h2bits(__half2 v) {
    union { __half2 h; unsigned u; } x; x.h = v; return x.u;
}

// bf16 m16n8k16 MMA, fp32 accumulate (layout validated: rel_err 0.0)
__device__ __forceinline__ void mma16816(float& c0, float& c1, float& c2, float& c3,
                                         unsigned a0, unsigned a1, unsigned a2, unsigned a3,
                                         unsigned b0, unsigned b1) {
    asm volatile(
        "mma.sync.aligned.m16n8k16.row.col.f32.bf16.bf16.f32 "
        "{%0,%1,%2,%3}, {%4,%5,%6,%7}, {%8,%9}, {%0,%1,%2,%3};"
        : "+f"(c0), "+f"(c1), "+f"(c2), "+f"(c3)
        : "r"(a0), "r"(a1), "r"(a2), "r"(a3), "r"(b0), "r"(b1));
}

// ---------------------------------------------------------------------------
// Prep: transpose z -> fp32 + bf16 scratch; exact zz (validated structure)
// ---------------------------------------------------------------------------
__global__ __launch_bounds__(TPB)
void prep_kernel(const float* __restrict__ z) {
    const int tid = threadIdx.x;
    const int p0  = blockIdx.x * TPB;
    const int b   = p0 / HW_;
    const int hw0 = p0 - b * HW_;
    const int p   = p0 + tid;
    const float* zp = z + (size_t)b * CHW_ + (hw0 + tid);

    float f[C_];
#pragma unroll
    for (int c = 0; c < C_; c++) f[c] = zp[(size_t)c * HW_];

    unsigned long long a0 = 0ull, a1 = 0ull;
#pragma unroll
    for (int c4 = 0; c4 < 16; c4++) {
        ffma2(a0, pack2(f[4*c4+0], f[4*c4+1]), pack2(f[4*c4+0], f[4*c4+1]));
        ffma2(a1, pack2(f[4*c4+2], f[4*c4+3]), pack2(f[4*c4+2], f[4*c4+3]));
    }
    float x, y, u, v;
    unpack2(a0, x, y); unpack2(a1, u, v);
    g_zz[p] = (x + y) + (u + v);

    float4* zf = (float4*)(g_zf32 + (size_t)p * C_);
#pragma unroll
    for (int i = 0; i < 16; i++)
        zf[i] = make_float4(f[4*i], f[4*i+1], f[4*i+2], f[4*i+3]);

    unsigned* zb = g_zbf + (size_t)p * (C_/2);
#pragma unroll
    for (int w = 0; w < 32; w++) zb[w] = bfpack(f[2*w], f[2*w+1]);
}

// ---------------------------------------------------------------------------
// Prep codebook: exact ee + bf16 conversion
// ---------------------------------------------------------------------------
__global__ void eprep_kernel(const float* __restrict__ ew) {
    int k = blockIdx.x * blockDim.x + threadIdx.x;
    if (k >= K_) return;
    const float4* r = reinterpret_cast<const float4*>(ew + (size_t)k * C_);
    float4 a = make_float4(0.f, 0.f, 0.f, 0.f);
    float f[C_];
#pragma unroll
    for (int c4 = 0; c4 < 16; c4++) {
        float4 e = r[c4];
        f[4*c4] = e.x; f[4*c4+1] = e.y; f[4*c4+2] = e.z; f[4*c4+3] = e.w;
        a.x = fmaf(e.x, e.x, a.x);
        a.y = fmaf(e.y, e.y, a.y);
        a.z = fmaf(e.z, e.z, a.z);
        a.w = fmaf(e.w, e.w, a.w);
    }
    g_ee[k] = (a.x + a.y) + (a.z + a.w);
    unsigned* eb = g_ebf + (size_t)k * (C_/2);
#pragma unroll
    for (int w = 0; w < 32; w++) eb[w] = bfpack(f[2*w], f[2*w+1]);
}

// ---------------------------------------------------------------------------
// Phase A: MMA screening (unchanged from validated R8 version).
// ---------------------------------------------------------------------------
__global__ __launch_bounds__(TPB)
void mma_kernel() {
    __shared__ unsigned esmw[CHUNK * 36];
    __shared__ float    see[CHUNK];

    const int tid  = threadIdx.x;
    const int lane = tid & 31;
    const int wid  = tid >> 5;
    const int g    = lane >> 2;
    const int tig  = lane & 3;
    const int p0   = blockIdx.x * TPB;

    unsigned afr[2][4][4];
#pragma unroll
    for (int mt = 0; mt < 2; mt++) {
#pragma unroll
        for (int ks = 0; ks < 4; ks++) {
            int row0 = p0 + wid * 32 + mt * 16 + g;
            int row1 = row0 + 8;
            const unsigned* z0 = g_zbf + (size_t)row0 * 32 + ks * 8 + tig;
            const unsigned* z1 = g_zbf + (size_t)row1 * 32 + ks * 8 + tig;
            afr[mt][ks][0] = z0[0];
            afr[mt][ks][1] = z1[0];
            afr[mt][ks][2] = z0[4];
            afr[mt][ks][3] = z1[4];
        }
    }

    float mn[2][2] = {{CUDART_INF_F, CUDART_INF_F}, {CUDART_INF_F, CUDART_INF_F}};

    for (int ch = 0; ch < NCH; ch++) {
        __syncthreads();
#pragma unroll
        for (int t = tid; t < CHUNK * 8; t += TPB) {
            int r = t >> 3, wg = t & 7;
            uint4 v = ((const uint4*)g_ebf)[(size_t)(ch * CHUNK + r) * 8 + wg];
            *((uint4*)(esmw + r * 36 + wg * 4)) = v;
        }
        if (tid < CHUNK) see[tid] = g_ee[ch * CHUNK + tid];
        __syncthreads();

        float acc[2][4][4];
#pragma unroll
        for (int mt = 0; mt < 2; mt++)
#pragma unroll
            for (int nt = 0; nt < 4; nt++)
#pragma unroll
                for (int i = 0; i < 4; i++) acc[mt][nt][i] = 0.f;

#pragma unroll
        for (int nt = 0; nt < 4; nt++) {
#pragma unroll
            for (int ks = 0; ks < 4; ks++) {
                unsigned b0 = esmw[(nt * 8 + g) * 36 + ks * 8 + tig];
                unsigned b1 = esmw[(nt * 8 + g) * 36 + ks * 8 + 4 + tig];
                mma16816(acc[0][nt][0], acc[0][nt][1], acc[0][nt][2], acc[0][nt][3],
                         afr[0][ks][0], afr[0][ks][1], afr[0][ks][2], afr[0][ks][3],
                         b0, b1);
                mma16816(acc[1][nt][0], acc[1][nt][1], acc[1][nt][2], acc[1][nt][3],
                         afr[1][ks][0], afr[1][ks][1], afr[1][ks][2], afr[1][ks][3],
                         b0, b1);
            }
        }

#pragma unroll
        for (int mt = 0; mt < 2; mt++) {
            int row0 = p0 + wid * 32 + mt * 16 + g;
#pragma unroll
            for (int nt = 0; nt < 4; nt++) {
                float eA = see[nt * 8 + 2 * tig];
                float eB = see[nt * 8 + 2 * tig + 1];
                float s0 = fmaf(-2.0f, acc[mt][nt][0], eA);
                float s1 = fmaf(-2.0f, acc[mt][nt][1], eB);
                float s2 = fmaf(-2.0f, acc[mt][nt][2], eA);
                float s3 = fmaf(-2.0f, acc[mt][nt][3], eB);
                mn[mt][0] = fminf(mn[mt][0], fminf(s0, s1));
                mn[mt][1] = fminf(mn[mt][1], fminf(s2, s3));
                size_t k8 = (size_t)(ch * 4 + nt);
                *(__half2*)(g_s + (k8 * NPTS + row0) * 8 + 2 * tig) =
                    __floats2half2_rn(s0, s1);
                *(__half2*)(g_s + (k8 * NPTS + row0 + 8) * 8 + 2 * tig) =
                    __floats2half2_rn(s2, s3);
            }
        }
    }

#pragma unroll
    for (int mt = 0; mt < 2; mt++) {
#pragma unroll
        for (int r = 0; r < 2; r++) {
            float v = mn[mt][r];
            v = fminf(v, __shfl_xor_sync(0xffffffffu, v, 1));
            v = fminf(v, __shfl_xor_sync(0xffffffffu, v, 2));
            if (tig == 0) {
                int row = p0 + wid * 32 + mt * 16 + g + r * 8;
                g_amin[row] = v;
            }
        }
    }
}

// ---------------------------------------------------------------------------
// Phase B: stream s~ with 4x-batched independent loads (MLP), filter, exact
// recheck (z loaded lazily — it's rare and L2-resident). Ascending k, strict
// '<': first-occurrence tiebreak, bit-identical exact pipeline.
// ---------------------------------------------------------------------------
__global__ __launch_bounds__(TPB)
void scan_kernel(const float* __restrict__ ew) {
    const int p = blockIdx.x * TPB + threadIdx.x;
    const float zz = g_zz[p];
    const float thresh = g_amin[p] + EPS;
    const __half th_h = __float2half_ru(thresh);   // round up: no misses
    const __half2 th2 = __halves2half2(th_h, th_h);

    const float4* zrow = (const float4*)(g_zf32 + (size_t)p * C_);

    float best = CUDART_INF_F;
    int   bidx = 0;

    // 4 independent 16B loads per iteration (32 codes)
    for (int k32 = 0; k32 < K_ / 32; k32++) {
        const int k8b = k32 * 4;
        uint4 v0 = *(const uint4*)(g_s + ((size_t)(k8b + 0) * NPTS + p) * 8);
        uint4 v1 = *(const uint4*)(g_s + ((size_t)(k8b + 1) * NPTS + p) * 8);
        uint4 v2 = *(const uint4*)(g_s + ((size_t)(k8b + 2) * NPTS + p) * 8);
        uint4 v3 = *(const uint4*)(g_s + ((size_t)(k8b + 3) * NPTS + p) * 8);

        uint4 vv[4] = {v0, v1, v2, v3};
        unsigned m = 0u;
#pragma unroll
        for (int q = 0; q < 4; q++) {
            m |= h2bits(__hlt2(*(__half2*)&vv[q].x, th2));
            m |= h2bits(__hlt2(*(__half2*)&vv[q].y, th2));
            m |= h2bits(__hlt2(*(__half2*)&vv[q].z, th2));
            m |= h2bits(__hlt2(*(__half2*)&vv[q].w, th2));
        }
        if (m == 0u) continue;

#pragma unroll
        for (int q = 0; q < 4; q++) {
            __half2 h0 = *(__half2*)&vv[q].x;
            __half2 h1 = *(__half2*)&vv[q].y;
            __half2 h2 = *(__half2*)&vv[q].z;
            __half2 h3 = *(__half2*)&vv[q].w;
            float sv[8];
            sv[0] = __low2float(h0); sv[1] = __high2float(h0);
            sv[2] = __low2float(h1); sv[3] = __high2float(h1);
            sv[4] = __low2float(h2); sv[5] = __high2float(h2);
            sv[6] = __low2float(h3); sv[7] = __high2float(h3);
#pragma unroll
            for (int j = 0; j < 8; j++) {
                if (sv[j] < thresh) {
                    int k = (k8b + q) * 8 + j;
                    // exact distance (validated bit-exact structure),
                    // z loaded here: rare path, L2-resident row
                    const float4* er = (const float4*)(ew + (size_t)k * C_);
                    unsigned long long a0 = 0ull, a1 = 0ull;
#pragma unroll
                    for (int c4 = 0; c4 < 16; c4++) {
                        float4 zv = __ldg(zrow + c4);
                        float4 ev = __ldg(er + c4);
                        ffma2(a0, pack2(zv.x, zv.y), pack2(ev.x, ev.y));
                        ffma2(a1, pack2(zv.z, zv.w), pack2(ev.z, ev.w));
                    }
                    float x, y, u, w;
                    unpack2(a0, x, y); unpack2(a1, u, w);
                    float dot = (x + y) + (u + w);
                    float d = fmaf(-2.0f, dot, zz + g_ee[k]);
                    if (d < best) { best = d; bidx = k; }
                }
            }
        }
    }

    g_bidx[p] = bidx;
}

// ---------------------------------------------------------------------------
// Outputs (validated R9 version): e-row gather via float4 into padded smem,
// transposed coalesced writes; loss partials exact.
// ---------------------------------------------------------------------------
__global__ __launch_bounds__(TPB)
void out_kernel(const float* __restrict__ z, const float* __restrict__ ew,
                float* __restrict__ out, int out_size) {
    __shared__ float sq[TPB][C_ + 1];
    __shared__ float sred[TPB];

    const int tid = threadIdx.x;
    const int p0  = blockIdx.x * TPB;
    const int b   = p0 / HW_;
    const int hw0 = p0 - b * HW_;
    const int p   = p0 + tid;

    const int bidx = g_bidx[p];

    const float4* zr   = (const float4*)(g_zf32 + (size_t)p * C_);
    const float4* erow = (const float4*)(ew + (size_t)bidx * C_);
    float4 al = make_float4(0.f, 0.f, 0.f, 0.f);
#pragma unroll
    for (int c4 = 0; c4 < 16; c4++) {
        float4 e  = __ldg(erow + c4);
        sq[tid][4*c4 + 0] = e.x;
        sq[tid][4*c4 + 1] = e.y;
        sq[tid][4*c4 + 2] = e.z;
        sq[tid][4*c4 + 3] = e.w;
        float4 zv = zr[c4];
        float dx = e.x - zv.x; al.x = fmaf(dx, dx, al.x);
        float dy = e.y - zv.y; al.y = fmaf(dy, dy, al.y);
        float dz = e.z - zv.z; al.z = fmaf(dz, dz, al.z);
        float dw = e.w - zv.w; al.w = fmaf(dw, dw, al.w);
    }
    sred[tid] = (al.x + al.y) + (al.z + al.w);
    __syncthreads();
#pragma unroll
    for (int s = TPB / 2; s > 0; s >>= 1) {
        if (tid < s) sred[tid] += sred[tid + s];
        __syncthreads();
    }
    if (tid == 0) g_partials[blockIdx.x] = sred[0];

    const size_t obase = (size_t)b * CHW_ + hw0;
#pragma unroll 4
    for (int c = 0; c < C_; c++) {
        size_t gi = obase + (size_t)c * HW_ + tid;
        float zv = z[gi];
        out[gi] = zv + (sq[tid][c] - zv);
    }

    if ((long long)out_size >= (long long)NPTS * C_ + NPTS)
        out[(size_t)NPTS * C_ + p0 + tid] = (float)bidx;
}

// ---------------------------------------------------------------------------
// Deterministic final loss reduction
// ---------------------------------------------------------------------------
__global__ void loss_kernel(float* __restrict__ out, int out_size) {
    __shared__ double sd[256];
    int tid = threadIdx.x;
    double s = 0.0;
#pragma unroll
    for (int j = 0; j < NBLK / 256; j++)
        s += (double)g_partials[tid * (NBLK / 256) + j];
    sd[tid] = s;
    __syncthreads();
#pragma unroll
    for (int st = 128; st > 0; st >>= 1) {
        if (tid < st) sd[tid] += sd[tid + st];
        __syncthreads();
    }
    if (tid == 0 && (long long)out_size >= (long long)NPTS * C_ + NPTS + 1)
        out[(size_t)NPTS * C_ + NPTS] =
            (float)(0.25 * sd[0] / (double)((size_t)NPTS * C_));
}

// ---------------------------------------------------------------------------
extern "C" void kernel_launch(void* const* d_in, const int* in_sizes, int n_in,
                              void* d_out, int out_size)
{
    const float* z  = (const float*)d_in[0];   // (32, 64, 64, 64) f32
    const float* ew = (const float*)d_in[1];   // (2048, 64) f32
    float* out = (float*)d_out;

    prep_kernel<<<NBLK, TPB>>>(z);
    eprep_kernel<<<(K_ + 127) / 128, 128>>>(ew);
    mma_kernel<<<NBLK, TPB>>>();
    scan_kernel<<<NBLK, TPB>>>(ew);
    out_kernel<<<NBLK, TPB>>>(z, ew, out, out_size);
    loss_kernel<<<1, 256>>>(out, out_size);
}